// round 17
// baseline (speedup 1.0000x reference)
#include <cuda_runtime.h>
#include <cuda_fp16.h>
#include <cstdint>

// SoftPixelCNN R17: two-vertex software pipeline per warp.
// Each warp owns vertices (2b, 2b+1). ALL global loads are front-batched:
// both nbr rows, both F-tiles (cp.async, double-buffered f[2], two commit
// groups), both coord gathers; then both W^T tiles + A-fragments. Drain:
// wait_group 1 -> mma/epilogue v0, wait_group 0 -> mma/epilogue v1.
// Stage buffer overlays wt[2] (dead after A-frags). Swizzles & fragment
// maps identical to R13-R16 (verified).

typedef unsigned u32;

#define MAXV 50176
__device__ __align__(16) uint4 g_hfeats[MAXV * 8];   // V x 64 fp16 (128 B rows)

__device__ __forceinline__ u32 pack_h2(float a, float b) {
    const __half2 h = __floats2half2_rn(a, b);
    return *(const u32*)&h;
}

__global__ __launch_bounds__(256)
void cvt_kernel(const float* __restrict__ feats, int n8)  // n8 = V*8
{
    const int i = blockIdx.x * blockDim.x + threadIdx.x;
    if (i >= n8) return;
    const float4 a = ((const float4*)feats)[2 * i];
    const float4 b = ((const float4*)feats)[2 * i + 1];
    uint4 r;
    r.x = pack_h2(a.x, a.y);
    r.y = pack_h2(a.z, a.w);
    r.z = pack_h2(b.x, b.y);
    r.w = pack_h2(b.z, b.w);
    g_hfeats[i] = r;
}

__device__ __forceinline__ u32 smem_u32(const void* p) {
    return (u32)__cvta_generic_to_shared(p);
}

#define LDSM_X4_TRANS(x0, x1, x2, x3, addr)                                   \
    asm volatile("ldmatrix.sync.aligned.m8n8.x4.trans.shared.b16 "            \
                 "{%0,%1,%2,%3}, [%4];"                                        \
                 : "=r"(x0), "=r"(x1), "=r"(x2), "=r"(x3) : "r"(addr))

#define MMA16816(c, a0, a1, a2, a3, b0, b1)                                   \
    asm volatile("mma.sync.aligned.m16n8k16.row.col.f32.f16.f16.f32 "         \
                 "{%0,%1,%2,%3}, {%4,%5,%6,%7}, {%8,%9}, {%0,%1,%2,%3};"       \
                 : "+f"((c)[0]), "+f"((c)[1]), "+f"((c)[2]), "+f"((c)[3])      \
                 : "r"(a0), "r"(a1), "r"(a2), "r"(a3), "r"(b0), "r"(b1))

__global__ __launch_bounds__(128, 5)
void spcnn_kernel(const float* __restrict__ coords,   // (V,4)
                  const int*   __restrict__ nbr,      // (V,32)
                  const float* __restrict__ ls,       // (1,)
                  float*       __restrict__ out,      // (V,576)
                  int V)
{
    const int warp = threadIdx.x >> 5;
    const int lane = threadIdx.x & 31;
    const int vbase = (blockIdx.x * 4 + warp) * 2;

    union WS {
        struct {
            __half wt[2][32][24];   // 3072 B: W^T per vertex, rows padded 48B
            __half f [2][32][64];   // 8192 B: F tiles, chunk-XOR swizzled
        } p;
        float stage[768];           // 3072 B: epilogue staging, overlays wt[2]
    };
    __shared__ __align__(16) WS ws[4];
    WS& S = ws[warp];

    if (vbase >= V) return;
    const int vB = (vbase + 1 < V) ? (vbase + 1) : (V - 1);
    const float g = 10.0f * ls[0];

    // ---------------- Step 1: both nbr rows (MLP=2) -----------------------------
    const int idx0 = nbr[vbase * 32 + lane];
    const int idx1 = nbr[vB    * 32 + lane];

    // ---------------- Step 2: both F tiles via cp.async (2 commit groups) -------
    {
        const int r0 = lane >> 3;
        const int c0 = lane & 7;
        const char* hf = (const char*)g_hfeats;
        #pragma unroll
        for (int b = 0; b < 2; ++b) {
            const int idxb = b ? idx1 : idx0;
            char* fs = (char*)S.p.f[b];
            #pragma unroll
            for (int it = 0; it < 8; ++it) {
                const int r = it * 4 + r0;
                const int n = __shfl_sync(0xFFFFFFFFu, idxb, r);
                const u32 dst = smem_u32(fs + r * 128 + ((c0 ^ (r & 7)) << 4));
                const char* src = hf + (size_t)n * 128 + c0 * 16;
                asm volatile("cp.async.cg.shared.global [%0], [%1], 16;"
                             :: "r"(dst), "l"(src));
            }
            asm volatile("cp.async.commit_group;" ::: "memory");
        }
    }

    // ---------------- Step 3: both phase-1s under the F-gather latency ----------
    #pragma unroll
    for (int b = 0; b < 2; ++b) {
        const int vv   = b ? vB   : vbase;
        const int idxb = b ? idx1 : idx0;
        const float4 cv = ((const float4*)coords)[vv];
        const float4 cn = ((const float4*)coords)[idxb];
        const float dx = cv.x - cn.x;
        const float dy = cv.y - cn.y;
        const float dz = cv.z - cn.z;
        const float dw = cv.w - cn.w;
        const float base = dx*dx + dy*dy + dz*dz + dw*dw;
        const float b1 = base + 1.0f;

        // OFFSETS (verified R1): o0=0 o1=-y o2=-x o3=-z o4=-w o5=+w o6=+z o7=+x o8=+y
        const float s = 0.03125f;   // 1/K folded into W
        const float w0 = s * __expf(-g * base);
        const float w1 = s * __expf(-g * (b1 - 2.0f * dy));
        const float w2 = s * __expf(-g * (b1 - 2.0f * dx));
        const float w3 = s * __expf(-g * (b1 - 2.0f * dz));
        const float w4 = s * __expf(-g * (b1 - 2.0f * dw));
        const float w5 = s * __expf(-g * (b1 + 2.0f * dw));
        const float w6 = s * __expf(-g * (b1 + 2.0f * dz));
        const float w7 = s * __expf(-g * (b1 + 2.0f * dx));
        const float w8 = s * __expf(-g * (b1 + 2.0f * dy));

        uint4 lo, hi;
        lo.x = pack_h2(w0, w1);
        lo.y = pack_h2(w2, w3);
        lo.z = pack_h2(w4, w5);
        lo.w = pack_h2(w6, w7);
        hi.x = pack_h2(w8, 0.0f);
        hi.y = 0u; hi.z = 0u; hi.w = 0u;
        *(uint4*)&S.p.wt[b][lane][0] = lo;
        *(uint4*)&S.p.wt[b][lane][8] = hi;
    }
    __syncwarp();

    // ---------------- Step 4: both A-fragment sets -------------------------------
    const int q  = lane >> 3;
    const int rr = lane & 7;
    const int lrA = ((q & 2) ? 8 : 0) + rr;
    const int lrB = ((q & 1) ? 8 : 0) + rr;
    const int chB = q >> 1;

    u32 a[2][2][4];
    #pragma unroll
    for (int b = 0; b < 2; ++b) {
        const u32 addrA0 = smem_u32(S.p.wt[b]) + (u32)(lrA * 48 + (q & 1) * 16);
        #pragma unroll
        for (int kt = 0; kt < 2; ++kt)
            LDSM_X4_TRANS(a[b][kt][0], a[b][kt][1], a[b][kt][2], a[b][kt][3],
                          addrA0 + kt * (16 * 48));
    }

    // ---------------- Step 5: drain — per-vertex mma + staged epilogue ----------
    const int tl = (lane & 15) >> 1;
    const int sl = 4 * (lane & 1);
    const int ol = lane >> 4;

    #pragma unroll
    for (int b = 0; b < 2; ++b) {
        if (b == 0) asm volatile("cp.async.wait_group 1;" ::: "memory");
        else        asm volatile("cp.async.wait_group 0;" ::: "memory");
        __syncwarp();   // cross-lane visibility of f[b]

        float c[8][4];
        #pragma unroll
        for (int t = 0; t < 8; ++t)
            #pragma unroll
            for (int j = 0; j < 4; ++j) c[t][j] = 0.0f;

        const u32 fb = smem_u32(S.p.f[b]);
        #pragma unroll
        for (int kt = 0; kt < 2; ++kt) {
            const u32 rowB = fb + (u32)((lrB + kt * 16) * 128);
            #pragma unroll
            for (int tp = 0; tp < 4; ++tp) {
                const int ch = chB + tp * 2;
                u32 b0, b1, b2, b3;
                LDSM_X4_TRANS(b0, b1, b2, b3, rowB + (u32)((ch ^ rr) << 4));
                MMA16816(c[2 * tp],     a[b][kt][0], a[b][kt][1], a[b][kt][2], a[b][kt][3], b0, b1);
                MMA16816(c[2 * tp + 1], a[b][kt][0], a[b][kt][1], a[b][kt][2], a[b][kt][3], b2, b3);
            }
        }

        // staged epilogue (stage overlays wt[2]; A-frags already in regs)
        __syncwarp();
        float* stg = S.stage;
        #pragma unroll
        for (int t = 0; t < 8; ++t)
            *(float2*)&stg[72 * t + 2 * lane] = make_float2(c[t][0], c[t][1]);
        if (lane < 4) {
            #pragma unroll
            for (int t = 0; t < 8; ++t)
                *(float2*)&stg[648 + 8 * t + 2 * lane] = make_float2(c[t][2], c[t][3]);
        }
        __syncwarp();

        const int vv = b ? vB : vbase;
        float* orow = out + (size_t)vv * 576;
        #pragma unroll
        for (int r = 0; r < 4; ++r) {
            const int o = 2 * r + ol;
            const float4 d = *(const float4*)&stg[72 * tl + 8 * o + sl];
            *(float4*)(orow + 128 * r + 4 * lane) = d;
        }
        if (lane < 16) {
            const float4 d = *(const float4*)&stg[648 + 8 * (lane >> 1) + 4 * (lane & 1)];
            *(float4*)(orow + 512 + 4 * lane) = d;
        }
        __syncwarp();   // stage reuse barrier for b=1
    }
}

extern "C" void kernel_launch(void* const* d_in, const int* in_sizes, int n_in,
                              void* d_out, int out_size)
{
    const float* coords = (const float*)d_in[0];
    const float* feats  = (const float*)d_in[1];
    const int*   nbr    = (const int*)  d_in[3];
    const float* ls     = (const float*)d_in[4];
    float* out = (float*)d_out;

    const int V = in_sizes[0] / 4;

    // pre-pass: fp32 -> fp16 feature table
    const int n8 = V * 8;
    cvt_kernel<<<(n8 + 255) / 256, 256>>>(feats, n8);

    const int verts_per_block = 8;    // 4 warps x 2 vertices
    const int blocks = (V + verts_per_block - 1) / verts_per_block;
    spcnn_kernel<<<blocks, 128>>>(coords, nbr, ls, out, V);
}